// round 9
// baseline (speedup 1.0000x reference)
#include <cuda_runtime.h>
#include <cuda_bf16.h>

// DecoderRNN on GB300 — fully fused per-row LSTM recurrence.
// R7 change: weight streaming was ~77% of the LTS (L2) cap and contending
// with the FMA pipe. Pack weights as bf16 (exact fp32 = bf16<<16 expansion,
// fp32 accumulation unchanged):
//   * g_W4b[k/2][t] = uint4 of 8 bf16 -> ONE LDG.128 per 2 k-steps
//   * expansion via shift/mask (ALU), no precision loss beyond the one-time
//     bf16 rounding of the weights at prep
// L2 traffic halves (~38% of cap) -> FMA-pipe-bound again.

typedef unsigned long long ull;

#define BATCH  65536
#define RB     16       // rows per block
#define RPAIR  8        // RB/2
#define HSTR   10       // padded k-major stride (ull) for sh_h / sh_z
#define NTH    256
#define NTT    4        // NT
#define NMM    11       // NM
#define SSS    4        // S
#define NEGBIG -1000000000.0f

__device__ uint4 g_W4b [128*256];   // [k/2][t]: 8 bf16 = 4 gates x 2 k  (W_hh)
__device__ uint4 g_W4zb[128*256];   // same for z-columns of W_ih
__device__ float g_Cbase[4*1024];   // [branch*2+aid][gate] = bid+aid+bias
__device__ float g_Gp  [16*1024];   // [prev][gate] action-emb contribution
__device__ float g_ent [2];         // raw entropy sums (t, m)

__device__ __forceinline__ ull dupf(float x){ ull r; asm("mov.b64 %0, {%1, %1};" : "=l"(r) : "f"(x)); return r; }
__device__ __forceinline__ ull packf(float x, float y){ ull r; asm("mov.b64 %0, {%1, %2};" : "=l"(r) : "f"(x), "f"(y)); return r; }
__device__ __forceinline__ float2 unpackf(ull v){ float2 r; asm("mov.b64 {%0, %1}, %2;" : "=f"(r.x), "=f"(r.y) : "l"(v)); return r; }
__device__ __forceinline__ void fma2(ull &d, ull a, ull b){ asm("fma.rn.f32x2 %0, %1, %2, %0;" : "+l"(d) : "l"(a), "l"(b)); }
// bf16 (packed pair) -> duplicated f32x2 operand; exact (bf16 = top 16 bits of f32)
__device__ __forceinline__ ull dup_lo(unsigned u){ return dupf(__uint_as_float(u<<16)); }
__device__ __forceinline__ ull dup_hi(unsigned u){ return dupf(__uint_as_float(u & 0xffff0000u)); }

__device__ __forceinline__ float sigf(float x){ return 1.0f/(1.0f + __expf(-x)); }
__device__ __forceinline__ float tanh_f(float x){ return 1.0f - 2.0f/(__expf(2.0f*x)+1.0f); }

// acc[gi][rp] (+)= sum_k W[k][t][gi] * hb[k][rp]   (packed row pairs, k-major h)
__device__ __forceinline__ void gemm256(const uint4* __restrict__ Wb,
                                        const ull* __restrict__ hb,
                                        int t, ull (&acc)[4][RPAIR])
{
  #pragma unroll 2
  for (int j=0;j<128;j++){            // j = k-pair
    uint4 u = Wb[(j<<8) + t];         // LDG.128 : 8 bf16
    const ull* hk = hb + (j*2)*HSTR;
    { // k = 2j
      ull w0 = dup_lo(u.x), w1 = dup_hi(u.x);
      ull w2 = dup_lo(u.y), w3 = dup_hi(u.y);
      ulonglong2 ha = *(const ulonglong2*)(hk+0);   // LDS.128 broadcast
      ulonglong2 hb2= *(const ulonglong2*)(hk+2);
      ulonglong2 hc = *(const ulonglong2*)(hk+4);
      ulonglong2 hd = *(const ulonglong2*)(hk+6);
      ull hp[RPAIR] = {ha.x,ha.y,hb2.x,hb2.y,hc.x,hc.y,hd.x,hd.y};
      #pragma unroll
      for (int rp=0;rp<RPAIR;rp++){
        fma2(acc[0][rp], w0, hp[rp]);
        fma2(acc[1][rp], w1, hp[rp]);
        fma2(acc[2][rp], w2, hp[rp]);
        fma2(acc[3][rp], w3, hp[rp]);
      }
    }
    { // k = 2j+1
      ull w0 = dup_lo(u.z), w1 = dup_hi(u.z);
      ull w2 = dup_lo(u.w), w3 = dup_hi(u.w);
      const ull* hk1 = hk + HSTR;
      ulonglong2 ha = *(const ulonglong2*)(hk1+0);
      ulonglong2 hb2= *(const ulonglong2*)(hk1+2);
      ulonglong2 hc = *(const ulonglong2*)(hk1+4);
      ulonglong2 hd = *(const ulonglong2*)(hk1+6);
      ull hp[RPAIR] = {ha.x,ha.y,hb2.x,hb2.y,hc.x,hc.y,hd.x,hd.y};
      #pragma unroll
      for (int rp=0;rp<RPAIR;rp++){
        fma2(acc[0][rp], w0, hp[rp]);
        fma2(acc[1][rp], w1, hp[rp]);
        fma2(acc[2][rp], w2, hp[rp]);
        fma2(acc[3][rp], w3, hp[rp]);
      }
    }
  }
}

// ---------------------------------------------------------------- prep ----
__device__ __forceinline__ unsigned pack_bf2(float lo, float hi){
  unsigned a = __bfloat16_as_ushort(__float2bfloat16_rn(lo));
  unsigned b = __bfloat16_as_ushort(__float2bfloat16_rn(hi));
  return a | (b<<16);
}

__global__ void prep_w4_kernel(const float* __restrict__ Wih, const float* __restrict__ Whh)
{
  int idx = blockIdx.x*blockDim.x + threadIdx.x;   // 32768 = 128j x 256t
  if (idx >= 128*256) return;
  int j = idx>>8, t = idx&255;
  int k0 = 2*j, k1 = 2*j+1;
  uint4 w;
  w.x = pack_bf2(Whh[( 0 +t)*256+k0], Whh[(256+t)*256+k0]);
  w.y = pack_bf2(Whh[(512+t)*256+k0], Whh[(768+t)*256+k0]);
  w.z = pack_bf2(Whh[( 0 +t)*256+k1], Whh[(256+t)*256+k1]);
  w.w = pack_bf2(Whh[(512+t)*256+k1], Whh[(768+t)*256+k1]);
  g_W4b[idx] = w;
  uint4 wz;
  wz.x = pack_bf2(Wih[( 0 +t)*448+k0], Wih[(256+t)*448+k0]);
  wz.y = pack_bf2(Wih[(512+t)*448+k0], Wih[(768+t)*448+k0]);
  wz.z = pack_bf2(Wih[( 0 +t)*448+k1], Wih[(256+t)*448+k1]);
  wz.w = pack_bf2(Wih[(512+t)*448+k1], Wih[(768+t)*448+k1]);
  g_W4zb[idx] = wz;
}

__global__ void prep_kernel(const float* __restrict__ Wih,
                            const float* __restrict__ bih, const float* __restrict__ bhh,
                            const float* __restrict__ aemb, const float* __restrict__ bemb,
                            const float* __restrict__ idemb)
{
  int g = blockIdx.x*blockDim.x + threadIdx.x;
  if (g==0){ g_ent[0]=0.f; g_ent[1]=0.f; }
  if (g>=1024) return;
  float bsum = bih[g]+bhh[g];
  float sb[2], sa[2];
  for (int br=0;br<2;br++){ float s=0.f; for(int e=0;e<64;e++) s += Wih[g*448+256+e]*bemb[br*64+e]; sb[br]=s; }
  for (int a=0;a<2;a++){ float s=0.f; for(int e=0;e<64;e++) s += Wih[g*448+320+e]*idemb[a*64+e]; sa[a]=s; }
  for (int br=0;br<2;br++)
    for (int a=0;a<2;a++)
      g_Cbase[(br*2+a)*1024+g] = bsum + sb[br] + sa[a];
  for (int p=0;p<16;p++){
    float s=0.f;
    for (int e=0;e<64;e++) s += Wih[g*448+384+e]*aemb[p*64+e];
    g_Gp[p*1024+g] = s;
  }
}

// ---------------------------------------------------------------- main ----
__global__ void __launch_bounds__(NTH,2) decoder_kernel(
  const float* __restrict__ z1, const float* __restrict__ z2,
  const int* __restrict__ t_act, const int* __restrict__ m_act,
  const float* __restrict__ Wt, const float* __restrict__ bt,
  const float* __restrict__ Wm, const float* __restrict__ bm,
  float* __restrict__ out)
{
  extern __shared__ ull smem_u[];
  ull* sh_h  = smem_u;                    // [256][HSTR] k-major packed h pairs
  ull* sh_z  = smem_u + 256*HSTR;         // [256][HSTR] k-major packed z pairs
  ull* sh_wz = smem_u + 2*256*HSTR;       // [4*RPAIR][256] per-thread Wz
  __shared__ int   s_pidx[RB];
  __shared__ int   s_mask[RB];
  __shared__ float s_lp[RB];
  __shared__ float s_red[16];

  const int t    = threadIdx.x;
  const int wid  = t>>5, lane = t&31;
  const int r0   = blockIdx.x*RB;

  float c[RB];
  #pragma unroll
  for (int r=0;r<RB;r++) c[r]=0.f;
  for (int i=t;i<256*HSTR;i+=NTH) sh_h[i]=0ull;
  if (t<RB){ s_pidx[t]=15; s_mask[t]=(1<<NTT)-1; s_lp[t]=0.f; }
  float eT=0.f, eM=0.f;

  for (int branch=0; branch<2; branch++){
    __syncthreads();   // protect s_mask / sh_z from previous phase
    const float* z = branch ? z2 : z1;
    for (int i=t;i<RB*256;i+=NTH){
      int rr=i>>8, k=i&255;
      ((float*)sh_z)[k*2*HSTR + rr] = z[(size_t)(r0+rr)*256+k];
    }
    if (t<RB) s_mask[t]=(1<<NTT)-1;
    __syncthreads();

    { // Wz = z @ W_ih[:, :256]^T  (per branch)
      ull acc[4][RPAIR];
      #pragma unroll
      for (int gi=0;gi<4;gi++)
        #pragma unroll
        for (int rp=0;rp<RPAIR;rp++) acc[gi][rp]=0ull;
      gemm256(g_W4zb, sh_z, t, acc);
      #pragma unroll
      for (int gi=0;gi<4;gi++)
        #pragma unroll
        for (int rp=0;rp<RPAIR;rp++) sh_wz[((gi*RPAIR+rp)<<8)+t]=acc[gi][rp];
    }

    for (int sub=0; sub<2*SSS; sub++){
      int step = sub>>1;
      int isM  = sub&1;
      __syncthreads();   // wz/pidx/h ready

      ull acc[4][RPAIR];
      { // gate init: Wz + Cbase + Gp[pidx]
        const float* Cb = g_Cbase + (branch*2+isM)*1024 + t;
        #pragma unroll
        for (int gi=0;gi<4;gi++){
          float cb = Cb[gi<<8];
          #pragma unroll
          for (int rp=0;rp<RPAIR;rp++){
            float2 wzv = unpackf(sh_wz[((gi*RPAIR+rp)<<8)+t]);
            int p0 = s_pidx[2*rp], p1 = s_pidx[2*rp+1];
            float gx = g_Gp[p0*1024 + (gi<<8) + t];
            float gy = g_Gp[p1*1024 + (gi<<8) + t];
            acc[gi][rp] = packf(wzv.x+cb+gx, wzv.y+cb+gy);
          }
        }
      }
      gemm256(g_W4b, sh_h, t, acc);
      __syncthreads();   // all reads of old h done

      // LSTM elementwise: thread t = hidden unit t; h stored k-major at k=t
      #pragma unroll
      for (int rp=0;rp<RPAIR;rp++){
        float2 gi_ = unpackf(acc[0][rp]);
        float2 gf_ = unpackf(acc[1][rp]);
        float2 gg_ = unpackf(acc[2][rp]);
        float2 go_ = unpackf(acc[3][rp]);
        int ra=2*rp, rb2=ra+1;
        c[ra]  = sigf(gf_.x)*c[ra]  + sigf(gi_.x)*tanh_f(gg_.x);
        c[rb2] = sigf(gf_.y)*c[rb2] + sigf(gi_.y)*tanh_f(gg_.y);
        float hx = sigf(go_.x)*tanh_f(c[ra]);
        float hy = sigf(go_.y)*tanh_f(c[rb2]);
        sh_h[t*HSTR + rp] = packf(hx,hy);
      }
      __syncthreads();   // h ready for heads

      // heads: warp w handles rows 2w, 2w+1; h[row r, unit k] = hbf[k*2*HSTR + r]
      const float* hbf = (const float*)sh_h;
      #pragma unroll
      for (int rr=0;rr<2;rr++){
        int r = (wid<<1)+rr;
        if (!isM){
          float a0=0.f,a1=0.f,a2=0.f,a3=0.f;
          #pragma unroll
          for (int kk=0;kk<8;kk++){
            int k = lane + (kk<<5);
            float hv = hbf[k*2*HSTR + r];
            a0 += Wt[      k]*hv;
            a1 += Wt[256 + k]*hv;
            a2 += Wt[512 + k]*hv;
            a3 += Wt[768 + k]*hv;
          }
          #pragma unroll
          for (int o=16;o;o>>=1){
            a0+=__shfl_xor_sync(0xffffffffu,a0,o);
            a1+=__shfl_xor_sync(0xffffffffu,a1,o);
            a2+=__shfl_xor_sync(0xffffffffu,a2,o);
            a3+=__shfl_xor_sync(0xffffffffu,a3,o);
          }
          int mk = s_mask[r];
          float l0 = (mk&1)? a0+bt[0] : NEGBIG;
          float l1 = (mk&2)? a1+bt[1] : NEGBIG;
          float l2 = (mk&4)? a2+bt[2] : NEGBIG;
          float l3 = (mk&8)? a3+bt[3] : NEGBIG;
          float mx = fmaxf(fmaxf(l0,l1),fmaxf(l2,l3));
          float e0=__expf(l0-mx), e1=__expf(l1-mx), e2=__expf(l2-mx), e3=__expf(l3-mx);
          float se = e0+e1+e2+e3;
          float sl = e0*l0+e1*l1+e2*l2+e3*l3;
          float lse = mx + __logf(se);
          int ta = t_act[(size_t)(r0+r)*8 + branch*4 + step];
          float lsel = (ta==0)? l0 : (ta==1)? l1 : (ta==2)? l2 : l3;
          float H = lse - sl/se;
          if (lane==0){
            s_lp[r]  += lsel - lse;
            s_mask[r] = mk & ~(1<<ta);
            s_pidx[r] = ta;            // LSTM#2 uses action_emb[ta]
            eT += H;
          }
        } else {
          float a[NMM];
          #pragma unroll
          for (int j=0;j<NMM;j++) a[j]=0.f;
          #pragma unroll
          for (int kk=0;kk<8;kk++){
            int k = lane + (kk<<5);
            float hv = hbf[k*2*HSTR + r];
            #pragma unroll
            for (int j=0;j<NMM;j++) a[j] += Wm[j*256+k]*hv;
          }
          #pragma unroll
          for (int j=0;j<NMM;j++){
            #pragma unroll
            for (int o=16;o;o>>=1) a[j]+=__shfl_xor_sync(0xffffffffu,a[j],o);
          }
          float mx = -1e30f;
          #pragma unroll
          for (int j=0;j<NMM;j++){ a[j]+=bm[j]; mx = fmaxf(mx,a[j]); }
          float se=0.f, sl=0.f;
          #pragma unroll
          for (int j=0;j<NMM;j++){ float e=__expf(a[j]-mx); se+=e; sl+=e*a[j]; }
          float lse = mx + __logf(se);
          int ma = m_act[(size_t)(r0+r)*8 + branch*4 + step];
          float lsel = a[0];
          #pragma unroll
          for (int j=1;j<NMM;j++) lsel = (j==ma)? a[j] : lsel;
          float H = lse - sl/se;
          if (lane==0){
            s_lp[r]  += lsel - lse;
            s_pidx[r] = ma;            // next step's prev
            eM += H;
          }
        }
      }
    }
  }

  __syncthreads();
  if (t<RB) out[r0+t] = s_lp[t];
  if (lane==0){ s_red[wid]=eT; s_red[8+wid]=eM; }
  __syncthreads();
  if (t==0){
    float sT=0.f,sM=0.f;
    for (int w=0;w<8;w++){ sT+=s_red[w]; sM+=s_red[8+w]; }
    atomicAdd(&g_ent[0],sT);
    atomicAdd(&g_ent[1],sM);
  }
}

// ----------------------------------------------------------- epilogue ----
__global__ void finalize_kernel(float* __restrict__ out, int off){
  if (threadIdx.x==0 && blockIdx.x==0){
    const float sc = 1.0f/(65536.0f*8.0f);  // mean over B, then /(2S)
    out[off]   = g_ent[0]*sc;
    out[off+1] = g_ent[1]*sc;
  }
}

__global__ void cvt_kernel(const int* __restrict__ ti, const int* __restrict__ mi,
                           float* __restrict__ out){
  int i = blockIdx.x*blockDim.x + threadIdx.x;
  if (i < 65536*8){
    out[65536 + i]           = (float)ti[i];
    out[65536 + 65536*8 + i] = (float)mi[i];
  }
}

// ---------------------------------------------------------------- host ----
extern "C" void kernel_launch(void* const* d_in, const int* in_sizes, int n_in,
                              void* d_out, int out_size)
{
  (void)in_sizes; (void)n_in;
  const float* z1    = (const float*)d_in[0];
  const float* z2    = (const float*)d_in[1];
  const int*   t_act = (const int*)  d_in[2];
  const int*   m_act = (const int*)  d_in[3];
  const float* aemb  = (const float*)d_in[4];
  const float* bemb  = (const float*)d_in[5];
  const float* idemb = (const float*)d_in[6];
  const float* Wih   = (const float*)d_in[7];
  const float* Whh   = (const float*)d_in[8];
  const float* bih   = (const float*)d_in[9];
  const float* bhh   = (const float*)d_in[10];
  const float* Wt    = (const float*)d_in[11];
  const float* bt    = (const float*)d_in[12];
  const float* Wm    = (const float*)d_in[13];
  const float* bm    = (const float*)d_in[14];
  float* out = (float*)d_out;

  const int SMEM_BYTES = (2*256*HSTR + 4*RPAIR*256) * (int)sizeof(ull); // 106496
  cudaFuncSetAttribute(decoder_kernel, cudaFuncAttributeMaxDynamicSharedMemorySize, SMEM_BYTES);

  prep_w4_kernel<<<128,256>>>(Wih, Whh);
  prep_kernel<<<4,256>>>(Wih,bih,bhh,aemb,bemb,idemb);
  decoder_kernel<<<BATCH/RB, NTH, SMEM_BYTES>>>(z1,z2,t_act,m_act,Wt,bt,Wm,bm,out);

  const int NACT = 65536*8;  // elements in t_actions (= m_actions)
  if (out_size >= 65536 + 2*NACT + 2){
    // tree-flatten layout: [log_p | t_actions | m_actions | t_ent | m_ent]
    cvt_kernel<<<(NACT+255)/256,256>>>(t_act, m_act, out);
    finalize_kernel<<<1,32>>>(out, 65536 + 2*NACT);
  } else if (out_size >= 65536 + 2){
    finalize_kernel<<<1,32>>>(out, 65536);
  }
  // else: log_p-only layout; main kernel already wrote out[0..B)
}

// round 11
// speedup vs baseline: 3.7934x; 3.7934x over previous
#include <cuda_runtime.h>
#include <cuda_bf16.h>
typedef unsigned short ush;

#define RB   64
#define NTH  512
#define ASTR 808
#define CSTR 257
#define KC   34
#define NMM  11
#define NEGBIG -1000000000.0f

__device__ uint2 g_Bfrag[KC*128*32];
__device__ float g_ent[2];

__device__ __forceinline__ unsigned su32(const void* p){
  unsigned r; asm("{.reg .u64 t; cvta.to.shared.u64 t, %1; cvt.u32.u64 %0, t;}" : "=r"(r) : "l"(p)); return r; }
__device__ __forceinline__ ush f2b(float x){ return __bfloat16_as_ushort(__float2bfloat16_rn(x)); }
__device__ __forceinline__ float b2f(ush u){ return __bfloat162float(__ushort_as_bfloat16(u)); }
__device__ __forceinline__ float tanha(float x){ float y; asm("tanh.approx.f32 %0, %1;" : "=f"(y) : "f"(x)); return y; }
__device__ __forceinline__ float sigf(float x){ return fmaf(0.5f, tanha(0.5f*x), 0.5f); }

#define LDSM4(r0,r1,r2,r3,a) asm volatile( \
  "ldmatrix.sync.aligned.m8n8.x4.shared.b16 {%0,%1,%2,%3},[%4];" \
  : "=r"(r0),"=r"(r1),"=r"(r2),"=r"(r3) : "r"(a))
#define MMA(d,a0,a1,a2,a3,b0,b1) asm( \
  "mma.sync.aligned.m16n8k16.row.col.f32.bf16.bf16.f32 {%0,%1,%2,%3},{%4,%5,%6,%7},{%8,%9},{%0,%1,%2,%3};" \
  : "+f"(d[0]),"+f"(d[1]),"+f"(d[2]),"+f"(d[3]) : "r"(a0),"r"(a1),"r"(a2),"r"(a3),"r"(b0),"r"(b1))

// B' rows: k<256 Wz, k<512 Whh, k<528 Gp, k<532 Cbase, else 0. col=4*unit+gate.
__device__ float wval(int k,int grow,const float* Wih,const float* Whh,const float* ae,
                      const float* be,const float* ie,const float* bi,const float* bh){
  if (k<256) return Wih[grow*448+k];
  if (k<512) return Whh[grow*256+(k-256)];
  if (k<528){ float s=0.f; int p=k-512; for(int e=0;e<64;e++) s+=Wih[grow*448+384+e]*ae[p*64+e]; return s; }
  if (k<532){ int s4=k-528,br=s4>>1,ad=s4&1; float s=bi[grow]+bh[grow];
    for(int e=0;e<64;e++) s+=Wih[grow*448+256+e]*be[br*64+e];
    for(int e=0;e<64;e++) s+=Wih[grow*448+320+e]*ie[ad*64+e]; return s; }
  return 0.f;
}
__device__ __forceinline__ unsigned pk2(float lo,float hi){
  return (unsigned)__bfloat16_as_ushort(__float2bfloat16_rn(lo)) |
         ((unsigned)__bfloat16_as_ushort(__float2bfloat16_rn(hi))<<16); }

__global__ void prep_bfrag(const float* Wih,const float* Whh,const float* ae,
                           const float* be,const float* ie,const float* bi,const float* bh){
  int idx = blockIdx.x*blockDim.x + threadIdx.x;
  if (idx==0){ g_ent[0]=0.f; g_ent[1]=0.f; }
  if (idx >= KC*128*32) return;
  int lane=idx&31, n8=(idx>>5)&127, kc=idx>>12;
  int n=(n8<<3)+(lane>>2), grow=(n&3)*256+(n>>2);
  int k0=(kc<<4)+((lane&3)<<1);
  uint2 b;
  b.x = pk2(wval(k0  ,grow,Wih,Whh,ae,be,ie,bi,bh), wval(k0+1,grow,Wih,Whh,ae,be,ie,bi,bh));
  b.y = pk2(wval(k0+8,grow,Wih,Whh,ae,be,ie,bi,bh), wval(k0+9,grow,Wih,Whh,ae,be,ie,bi,bh));
  g_Bfrag[idx]=b;
}

__global__ void __launch_bounds__(NTH,1) decoder_kernel(
  const float* __restrict__ z1, const float* __restrict__ z2,
  const int* __restrict__ t_act, const int* __restrict__ m_act,
  const float* __restrict__ Wt, const float* __restrict__ bt,
  const float* __restrict__ Wm, const float* __restrict__ bm,
  float* __restrict__ out)
{
  extern __shared__ ush A[];                 // [64][ASTR] bf16
  float* Csm = (float*)(A + RB*ASTR);        // [64][CSTR] f32
  __shared__ int   s_pidx[RB], s_mask[RB];
  __shared__ float s_lp[RB], s_red[32];

  const int t=threadIdx.x, wid=t>>5, lane=t&31;
  const int r0=blockIdx.x*RB;
  const unsigned abase=su32(A);
  const int rowA=lane&15, kadj=(lane>>4)<<3;
  float eT=0.f, eM=0.f;

  for (int i=t;i<RB*ASTR;i+=NTH) A[i]=0;
  for (int i=t;i<RB*CSTR;i+=NTH) Csm[i]=0.f;
  for (int i=t;i<RB*256;i+=NTH)
    A[(i>>8)*ASTR+(i&255)] = f2b(z1[(size_t)(r0+(i>>8))*256+(i&255)]);
  if (t<RB){ s_pidx[t]=15; s_mask[t]=15; s_lp[t]=0.f;
             A[t*ASTR+768+15]=0x3F80; A[t*ASTR+784]=0x3F80; }

  for (int ss=0; ss<16; ss++){
    const int hin = 256+((ss&1)<<8), hout = 256+((1-(ss&1))<<8);
    __syncthreads();
    #pragma unroll 1
    for (int pass=0; pass<2; pass++){
      float acc[4][4][4];
      #pragma unroll
      for (int j=0;j<4;j++)
        #pragma unroll
        for (int m=0;m<4;m++){ acc[j][m][0]=0.f; acc[j][m][1]=0.f; acc[j][m][2]=0.f; acc[j][m][3]=0.f; }
      const int n8b = (pass<<6)+(wid<<2);
      #pragma unroll 2
      for (int kc=0;kc<KC;kc++){
        int kb = kc<16 ? (kc<<4) : (kc<32 ? hin+((kc-16)<<4) : (kc==32?768:784));
        unsigned a0[4],a1[4],a2[4],a3[4];
        #pragma unroll
        for (int m=0;m<4;m++){
          unsigned aa = abase + (unsigned)((((m<<4)+rowA)*ASTR + kb + kadj)<<1);
          LDSM4(a0[m],a1[m],a2[m],a3[m],aa);
        }
        const uint2* bp = g_Bfrag + ((size_t)(kc<<7)+n8b)*32 + lane;
        #pragma unroll
        for (int j=0;j<4;j++){
          uint2 b = bp[j<<5];
          #pragma unroll
          for (int m=0;m<4;m++) MMA(acc[j][m],a0[m],a1[m],a2[m],a3[m],b.x,b.y);
        }
      }
      #pragma unroll
      for (int j=0;j<4;j++){
        int n8=n8b+j;
        #pragma unroll
        for (int m=0;m<4;m++){
          float c0=acc[j][m][0],c1=acc[j][m][1],c2=acc[j][m][2],c3=acc[j][m][3];
          float g0=__shfl_xor_sync(~0u,c0,1), g1=__shfl_xor_sync(~0u,c1,1);
          float g2=__shfl_xor_sync(~0u,c2,1), g3=__shfl_xor_sync(~0u,c3,1);
          if (!(lane&1)){
            int u=(n8<<1)|((lane>>1)&1), ra=(m<<4)+(lane>>2);
            float cn = sigf(c1)*Csm[ra*CSTR+u] + sigf(c0)*tanha(g0);
            Csm[ra*CSTR+u]=cn; A[ra*ASTR+hout+u]=f2b(sigf(g1)*tanha(cn));
            int rb=ra+8;
            float cm = sigf(c3)*Csm[rb*CSTR+u] + sigf(c2)*tanha(g2);
            Csm[rb*CSTR+u]=cm; A[rb*ASTR+hout+u]=f2b(sigf(g3)*tanha(cm));
          }
        }
      }
    }
    __syncthreads();

    const int branch=ss>>3, isM=ss&1, step=(ss>>1)&3;
    for (int rr=0;rr<4;rr++){
      int r=(wid<<2)+rr;
      const ush* hr = A + r*ASTR + hout;
      if (!isM){
        float a0=0.f,a1=0.f,a2=0.f,a3=0.f;
        #pragma unroll
        for (int kk=0;kk<8;kk++){
          int k=lane+(kk<<5); float hv=b2f(hr[k]);
          a0+=Wt[k]*hv; a1+=Wt[256+k]*hv; a2+=Wt[512+k]*hv; a3+=Wt[768+k]*hv;
        }
        #pragma unroll
        for (int o=16;o;o>>=1){
          a0+=__shfl_xor_sync(~0u,a0,o); a1+=__shfl_xor_sync(~0u,a1,o);
          a2+=__shfl_xor_sync(~0u,a2,o); a3+=__shfl_xor_sync(~0u,a3,o);
        }
        int mk=s_mask[r];
        float l0=(mk&1)?a0+bt[0]:NEGBIG, l1=(mk&2)?a1+bt[1]:NEGBIG;
        float l2=(mk&4)?a2+bt[2]:NEGBIG, l3=(mk&8)?a3+bt[3]:NEGBIG;
        float mx=fmaxf(fmaxf(l0,l1),fmaxf(l2,l3));
        float e0=__expf(l0-mx),e1=__expf(l1-mx),e2=__expf(l2-mx),e3=__expf(l3-mx);
        float se=e0+e1+e2+e3, sl=e0*l0+e1*l1+e2*l2+e3*l3, lse=mx+__logf(se);
        int ta=t_act[(size_t)(r0+r)*8+branch*4+step];
        float lsel=(ta==0)?l0:(ta==1)?l1:(ta==2)?l2:l3;
        if (lane==0){
          s_lp[r]+=lsel-lse; s_mask[r]=mk&~(1<<ta); eT+=lse-sl/se;
          A[r*ASTR+768+s_pidx[r]]=0; A[r*ASTR+768+ta]=0x3F80; s_pidx[r]=ta;
        }
      } else {
        float a[NMM];
        #pragma unroll
        for (int j=0;j<NMM;j++) a[j]=0.f;
        #pragma unroll
        for (int kk=0;kk<8;kk++){
          int k=lane+(kk<<5); float hv=b2f(hr[k]);
          #pragma unroll
          for (int j=0;j<NMM;j++) a[j]+=Wm[j*256+k]*hv;
        }
        #pragma unroll
        for (int j=0;j<NMM;j++)
          #pragma unroll
          for (int o=16;o;o>>=1) a[j]+=__shfl_xor_sync(~0u,a[j],o);
        float mx=-1e30f;
        #pragma unroll
        for (int j=0;j<NMM;j++){ a[j]+=bm[j]; mx=fmaxf(mx,a[j]); }
        float se=0.f,sl=0.f;
        #pragma unroll
        for (int j=0;j<NMM;j++){ float e=__expf(a[j]-mx); se+=e; sl+=e*a[j]; }
        float lse=mx+__logf(se);
        int ma=m_act[(size_t)(r0+r)*8+branch*4+step];
        float lsel=a[0];
        #pragma unroll
        for (int j=1;j<NMM;j++) lsel=(j==ma)?a[j]:lsel;
        if (lane==0){
          s_lp[r]+=lsel-lse; eM+=lse-sl/se;
          A[r*ASTR+768+s_pidx[r]]=0; A[r*ASTR+768+ma]=0x3F80; s_pidx[r]=ma;
        }
      }
    }
    if (ss<15 && t<RB){
      int sc=((ss>>3)<<1)|(ss&1), sn=(((ss+1)>>3)<<1)|((ss+1)&1);
      A[t*ASTR+784+sc]=0; A[t*ASTR+784+sn]=0x3F80;
    }
    if (ss==7){
      for (int i=t;i<RB*256;i+=NTH)
        A[(i>>8)*ASTR+(i&255)] = f2b(z2[(size_t)(r0+(i>>8))*256+(i&255)]);
      if (t<RB) s_mask[t]=15;
    }
  }

  __syncthreads();
  if (t<RB) out[r0+t]=s_lp[t];
  if (lane==0){ s_red[wid]=eT; s_red[16+wid]=eM; }
  __syncthreads();
  if (t==0){
    float sT=0.f,sM=0.f;
    for (int w=0;w<16;w++){ sT+=s_red[w]; sM+=s_red[16+w]; }
    atomicAdd(&g_ent[0],sT); atomicAdd(&g_ent[1],sM);
  }
}

__global__ void finalize_kernel(float* out,int off){
  if (threadIdx.x==0 && blockIdx.x==0){
    const float sc=1.0f/(65536.0f*8.0f);
    out[off]=g_ent[0]*sc; out[off+1]=g_ent[1]*sc;
  }
}
__global__ void cvt_kernel(const int* ti,const int* mi,float* out){
  int i=blockIdx.x*blockDim.x+threadIdx.x;
  if (i<65536*8){ out[65536+i]=(float)ti[i]; out[65536+65536*8+i]=(float)mi[i]; }
}

extern "C" void kernel_launch(void* const* d_in, const int* in_sizes, int n_in,
                              void* d_out, int out_size)
{
  (void)in_sizes; (void)n_in;
  const float* z1=(const float*)d_in[0];  const float* z2=(const float*)d_in[1];
  const int* t_act=(const int*)d_in[2];   const int* m_act=(const int*)d_in[3];
  const float* aemb=(const float*)d_in[4];const float* bemb=(const float*)d_in[5];
  const float* idemb=(const float*)d_in[6];
  const float* Wih=(const float*)d_in[7]; const float* Whh=(const float*)d_in[8];
  const float* bih=(const float*)d_in[9]; const float* bhh=(const float*)d_in[10];
  const float* Wt=(const float*)d_in[11]; const float* bt=(const float*)d_in[12];
  const float* Wm=(const float*)d_in[13]; const float* bm=(const float*)d_in[14];
  float* out=(float*)d_out;

  const int SMEM = RB*ASTR*2 + RB*CSTR*4;   // 169216 B
  cudaFuncSetAttribute(decoder_kernel, cudaFuncAttributeMaxDynamicSharedMemorySize, SMEM);

  prep_bfrag<<<(KC*128*32+255)/256,256>>>(Wih,Whh,aemb,bemb,idemb,bih,bhh);
  decoder_kernel<<<65536/RB, NTH, SMEM>>>(z1,z2,t_act,m_act,Wt,bt,Wm,bm,out);

  const int NACT=65536*8;
  if (out_size >= 65536+2*NACT+2){
    cvt_kernel<<<(NACT+255)/256,256>>>(t_act,m_act,out);
    finalize_kernel<<<1,32>>>(out,65536+2*NACT);
  } else if (out_size >= 65536+2){
    finalize_kernel<<<1,32>>>(out,65536);
  }
}

// round 12
// speedup vs baseline: 4.0803x; 1.0756x over previous
#include <cuda_runtime.h>
#include <cuda_bf16.h>
typedef unsigned short ush;

#define RB   64
#define NTH  512
#define ASTR 808
#define CSTR 258
#define KC   34
#define NMM  11
#define NEGBIG -1000000000.0f

__device__ uint4 g_Bp[KC*64*32];   // [kc][n8pair][lane] two b-fragments packed
__device__ float g_ent[2];

__device__ __forceinline__ unsigned su32(const void* p){
  unsigned r; asm("{.reg .u64 t; cvta.to.shared.u64 t, %1; cvt.u32.u64 %0, t;}" : "=r"(r) : "l"(p)); return r; }
__device__ __forceinline__ ush f2b(float x){ return __bfloat16_as_ushort(__float2bfloat16_rn(x)); }
__device__ __forceinline__ float b2f(ush u){ return __bfloat162float(__ushort_as_bfloat16(u)); }
__device__ __forceinline__ float tanha(float x){ float y; asm("tanh.approx.f32 %0, %1;" : "=f"(y) : "f"(x)); return y; }
__device__ __forceinline__ float sigf(float x){ return fmaf(0.5f, tanha(0.5f*x), 0.5f); }

#define LDSM4(r0,r1,r2,r3,a) asm volatile( \
  "ldmatrix.sync.aligned.m8n8.x4.shared.b16 {%0,%1,%2,%3},[%4];" \
  : "=r"(r0),"=r"(r1),"=r"(r2),"=r"(r3) : "r"(a))
#define MMA(d,a0,a1,a2,a3,b0,b1) asm( \
  "mma.sync.aligned.m16n8k16.row.col.f32.bf16.bf16.f32 {%0,%1,%2,%3},{%4,%5,%6,%7},{%8,%9},{%0,%1,%2,%3};" \
  : "+f"(d[0]),"+f"(d[1]),"+f"(d[2]),"+f"(d[3]) : "r"(a0),"r"(a1),"r"(a2),"r"(a3),"r"(b0),"r"(b1))

// B' rows: k<256 Wz, k<512 Whh, k<528 Gp, k<532 Cbase, else 0. col=4*unit+gate.
__device__ float wval(int k,int grow,const float* Wih,const float* Whh,const float* ae,
                      const float* be,const float* ie,const float* bi,const float* bh){
  if (k<256) return Wih[grow*448+k];
  if (k<512) return Whh[grow*256+(k-256)];
  if (k<528){ float s=0.f; int p=k-512; for(int e=0;e<64;e++) s+=Wih[grow*448+384+e]*ae[p*64+e]; return s; }
  if (k<532){ int s4=k-528,br=s4>>1,ad=s4&1; float s=bi[grow]+bh[grow];
    for(int e=0;e<64;e++) s+=Wih[grow*448+256+e]*be[br*64+e];
    for(int e=0;e<64;e++) s+=Wih[grow*448+320+e]*ie[ad*64+e]; return s; }
  return 0.f;
}
__device__ __forceinline__ unsigned pk2(float lo,float hi){
  return (unsigned)__bfloat16_as_ushort(__float2bfloat16_rn(lo)) |
         ((unsigned)__bfloat16_as_ushort(__float2bfloat16_rn(hi))<<16); }

__global__ void prep_bfrag(const float* Wih,const float* Whh,const float* ae,
                           const float* be,const float* ie,const float* bi,const float* bh){
  int idx = blockIdx.x*blockDim.x + threadIdx.x;
  if (idx==0){ g_ent[0]=0.f; g_ent[1]=0.f; }
  if (idx >= KC*64*32) return;
  int lane=idx&31, np=(idx>>5)&63, kc=idx>>11;
  int k0=(kc<<4)+((lane&3)<<1);
  uint4 b;
  #pragma unroll
  for (int s=0;s<2;s++){
    int n8=(np<<1)+s;
    int n=(n8<<3)+(lane>>2), grow=(n&3)*256+(n>>2);
    unsigned fx = pk2(wval(k0  ,grow,Wih,Whh,ae,be,ie,bi,bh), wval(k0+1,grow,Wih,Whh,ae,be,ie,bi,bh));
    unsigned fy = pk2(wval(k0+8,grow,Wih,Whh,ae,be,ie,bi,bh), wval(k0+9,grow,Wih,Whh,ae,be,ie,bi,bh));
    if (s==0){ b.x=fx; b.y=fy; } else { b.z=fx; b.w=fy; }
  }
  g_Bp[idx]=b;
}

__global__ void __launch_bounds__(NTH,1) decoder_kernel(
  const float* __restrict__ z1, const float* __restrict__ z2,
  const int* __restrict__ t_act, const int* __restrict__ m_act,
  const float* __restrict__ Wt, const float* __restrict__ bt,
  const float* __restrict__ Wm, const float* __restrict__ bm,
  float* __restrict__ out)
{
  extern __shared__ ush A[];                 // [64][ASTR] bf16
  float* Csm = (float*)(A + RB*ASTR);        // [64][CSTR] f32
  __shared__ int   s_pidx[RB], s_mask[RB];
  __shared__ float s_lp[RB], s_red[32];

  const int t=threadIdx.x, wid=t>>5, lane=t&31;
  const int r0=blockIdx.x*RB;
  const unsigned abase=su32(A);
  const int rowA=lane&15, kadj=(lane>>4)<<3;
  const int mtb=(wid>>3)<<1;       // first m-tile for this warp (0 or 2)
  const int n8w=(wid&7)<<3;        // n8 base within pass
  float eT=0.f, eM=0.f;

  for (int i=t;i<RB*ASTR;i+=NTH) A[i]=0;
  for (int i=t;i<RB*CSTR;i+=NTH) Csm[i]=0.f;
  for (int i=t;i<RB*256;i+=NTH)
    A[(i>>8)*ASTR+(i&255)] = f2b(z1[(size_t)(r0+(i>>8))*256+(i&255)]);
  if (t<RB){ s_pidx[t]=15; s_mask[t]=15; s_lp[t]=0.f;
             A[t*ASTR+768+15]=0x3F80; A[t*ASTR+784]=0x3F80; }

  for (int ss=0; ss<16; ss++){
    const int hin = 256+((ss&1)<<8), hout = 256+((1-(ss&1))<<8);
    __syncthreads();
    #pragma unroll 1
    for (int pass=0; pass<2; pass++){
      const int n8b = (pass<<6)+n8w;
      float acc[8][2][4];
      #pragma unroll
      for (int j=0;j<8;j++)
        #pragma unroll
        for (int m=0;m<2;m++){ acc[j][m][0]=0.f; acc[j][m][1]=0.f; acc[j][m][2]=0.f; acc[j][m][3]=0.f; }
      #pragma unroll 2
      for (int kc=0;kc<KC;kc++){
        int kb = kc<16 ? (kc<<4) : (kc<32 ? hin+((kc-16)<<4) : (kc==32?768:784));
        unsigned a0[2],a1[2],a2[2],a3[2];
        #pragma unroll
        for (int m=0;m<2;m++){
          unsigned aa = abase + (unsigned)(((((mtb+m)<<4)+rowA)*ASTR + kb + kadj)<<1);
          LDSM4(a0[m],a1[m],a2[m],a3[m],aa);
        }
        const uint4* bp = g_Bp + ((size_t)(kc<<6)+(n8b>>1))*32 + lane;
        #pragma unroll
        for (int jp=0;jp<4;jp++){
          uint4 b = bp[jp<<5];
          #pragma unroll
          for (int m=0;m<2;m++){
            MMA(acc[2*jp  ][m], a0[m],a1[m],a2[m],a3[m], b.x, b.y);
            MMA(acc[2*jp+1][m], a0[m],a1[m],a2[m],a3[m], b.z, b.w);
          }
        }
      }
      #pragma unroll
      for (int j=0;j<8;j++){
        int n8=n8b+j;
        #pragma unroll
        for (int m=0;m<2;m++){
          float c0=acc[j][m][0],c1=acc[j][m][1],c2=acc[j][m][2],c3=acc[j][m][3];
          float t0=__shfl_xor_sync(~0u,c0,1), t1=__shfl_xor_sync(~0u,c1,1);
          float t2=__shfl_xor_sync(~0u,c2,1), t3=__shfl_xor_sync(~0u,c3,1);
          // even lanes: row ra (own i,f = c0,c1; g,o from odd = t0,t1)
          // odd  lanes: row rb (i,f from even = t2,t3; own g,o = c2,c3)
          float gi_,gf_,gg_,go_; int row;
          if (lane&1){ gi_=t2; gf_=t3; gg_=c2; go_=c3; row=((mtb+m)<<4)+(lane>>2)+8; }
          else       { gi_=c0; gf_=c1; gg_=t0; go_=t1; row=((mtb+m)<<4)+(lane>>2); }
          int u=(n8<<1)|((lane>>1)&1);
          float cn = sigf(gf_)*Csm[row*CSTR+u] + sigf(gi_)*tanha(gg_);
          Csm[row*CSTR+u]=cn;
          A[row*ASTR+hout+u]=f2b(sigf(go_)*tanha(cn));
        }
      }
    }
    __syncthreads();

    const int branch=ss>>3, isM=ss&1, step=(ss>>1)&3;
    for (int rr=0;rr<4;rr++){
      int r=(wid<<2)+rr;
      const ush* hr = A + r*ASTR + hout;
      if (!isM){
        float a0=0.f,a1=0.f,a2=0.f,a3=0.f;
        #pragma unroll
        for (int kk=0;kk<8;kk++){
          int k=lane+(kk<<5); float hv=b2f(hr[k]);
          a0+=Wt[k]*hv; a1+=Wt[256+k]*hv; a2+=Wt[512+k]*hv; a3+=Wt[768+k]*hv;
        }
        #pragma unroll
        for (int o=16;o;o>>=1){
          a0+=__shfl_xor_sync(~0u,a0,o); a1+=__shfl_xor_sync(~0u,a1,o);
          a2+=__shfl_xor_sync(~0u,a2,o); a3+=__shfl_xor_sync(~0u,a3,o);
        }
        int mk=s_mask[r];
        float l0=(mk&1)?a0+bt[0]:NEGBIG, l1=(mk&2)?a1+bt[1]:NEGBIG;
        float l2=(mk&4)?a2+bt[2]:NEGBIG, l3=(mk&8)?a3+bt[3]:NEGBIG;
        float mx=fmaxf(fmaxf(l0,l1),fmaxf(l2,l3));
        float e0=__expf(l0-mx),e1=__expf(l1-mx),e2=__expf(l2-mx),e3=__expf(l3-mx);
        float se=e0+e1+e2+e3, sl=e0*l0+e1*l1+e2*l2+e3*l3, lse=mx+__logf(se);
        int ta=t_act[(size_t)(r0+r)*8+branch*4+step];
        float lsel=(ta==0)?l0:(ta==1)?l1:(ta==2)?l2:l3;
        if (lane==0){
          s_lp[r]+=lsel-lse; s_mask[r]=mk&~(1<<ta); eT+=lse-sl/se;
          A[r*ASTR+768+s_pidx[r]]=0; A[r*ASTR+768+ta]=0x3F80; s_pidx[r]=ta;
        }
      } else {
        float a[NMM];
        #pragma unroll
        for (int j=0;j<NMM;j++) a[j]=0.f;
        #pragma unroll
        for (int kk=0;kk<8;kk++){
          int k=lane+(kk<<5); float hv=b2f(hr[k]);
          #pragma unroll
          for (int j=0;j<NMM;j++) a[j]+=Wm[j*256+k]*hv;
        }
        #pragma unroll
        for (int j=0;j<NMM;j++)
          #pragma unroll
          for (int o=16;o;o>>=1) a[j]+=__shfl_xor_sync(~0u,a[j],o);
        float mx=-1e30f;
        #pragma unroll
        for (int j=0;j<NMM;j++){ a[j]+=bm[j]; mx=fmaxf(mx,a[j]); }
        float se=0.f,sl=0.f;
        #pragma unroll
        for (int j=0;j<NMM;j++){ float e=__expf(a[j]-mx); se+=e; sl+=e*a[j]; }
        float lse=mx+__logf(se);
        int ma=m_act[(size_t)(r0+r)*8+branch*4+step];
        float lsel=a[0];
        #pragma unroll
        for (int j=1;j<NMM;j++) lsel=(j==ma)?a[j]:lsel;
        if (lane==0){
          s_lp[r]+=lsel-lse; eM+=lse-sl/se;
          A[r*ASTR+768+s_pidx[r]]=0; A[r*ASTR+768+ma]=0x3F80; s_pidx[r]=ma;
        }
      }
    }
    if (ss<15 && t<RB){
      int sc=((ss>>3)<<1)|(ss&1), sn=(((ss+1)>>3)<<1)|((ss+1)&1);
      A[t*ASTR+784+sc]=0; A[t*ASTR+784+sn]=0x3F80;
    }
    if (ss==7){
      for (int i=t;i<RB*256;i+=NTH)
        A[(i>>8)*ASTR+(i&255)] = f2b(z2[(size_t)(r0+(i>>8))*256+(i&255)]);
      if (t<RB) s_mask[t]=15;
    }
  }

  __syncthreads();
  if (t<RB) out[r0+t]=s_lp[t];
  if (lane==0){ s_red[wid]=eT; s_red[16+wid]=eM; }
  __syncthreads();
  if (t==0){
    float sT=0.f,sM=0.f;
    for (int w=0;w<16;w++){ sT+=s_red[w]; sM+=s_red[16+w]; }
    atomicAdd(&g_ent[0],sT); atomicAdd(&g_ent[1],sM);
  }
}

__global__ void finalize_kernel(float* out,int off){
  if (threadIdx.x==0 && blockIdx.x==0){
    const float sc=1.0f/(65536.0f*8.0f);
    out[off]=g_ent[0]*sc; out[off+1]=g_ent[1]*sc;
  }
}
__global__ void cvt_kernel(const int* ti,const int* mi,float* out){
  int i=blockIdx.x*blockDim.x+threadIdx.x;
  if (i<65536*8){ out[65536+i]=(float)ti[i]; out[65536+65536*8+i]=(float)mi[i]; }
}

extern "C" void kernel_launch(void* const* d_in, const int* in_sizes, int n_in,
                              void* d_out, int out_size)
{
  (void)in_sizes; (void)n_in;
  const float* z1=(const float*)d_in[0];  const float* z2=(const float*)d_in[1];
  const int* t_act=(const int*)d_in[2];   const int* m_act=(const int*)d_in[3];
  const float* aemb=(const float*)d_in[4];const float* bemb=(const float*)d_in[5];
  const float* idemb=(const float*)d_in[6];
  const float* Wih=(const float*)d_in[7]; const float* Whh=(const float*)d_in[8];
  const float* bih=(const float*)d_in[9]; const float* bhh=(const float*)d_in[10];
  const float* Wt=(const float*)d_in[11]; const float* bt=(const float*)d_in[12];
  const float* Wm=(const float*)d_in[13]; const float* bm=(const float*)d_in[14];
  float* out=(float*)d_out;

  const int SMEM = RB*ASTR*2 + RB*CSTR*4;
  cudaFuncSetAttribute(decoder_kernel, cudaFuncAttributeMaxDynamicSharedMemorySize, SMEM);

  prep_bfrag<<<(KC*64*32+255)/256,256>>>(Wih,Whh,aemb,bemb,idemb,bih,bhh);
  decoder_kernel<<<65536/RB, NTH, SMEM>>>(z1,z2,t_act,m_act,Wt,bt,Wm,bm,out);

  const int NACT=65536*8;
  if (out_size >= 65536+2*NACT+2){
    cvt_kernel<<<(NACT+255)/256,256>>>(t_act,m_act,out);
    finalize_kernel<<<1,32>>>(out,65536+2*NACT);
  } else if (out_size >= 65536+2){
    finalize_kernel<<<1,32>>>(out,65536);
  }
}

// round 13
// speedup vs baseline: 5.5925x; 1.3706x over previous
#include <cuda_runtime.h>
#include <cuda_bf16.h>
typedef unsigned short ush;

#define RB   64
#define NTH  512
#define ASTR 808
#define CSTR 258
#define KC   34
#define NMM  11
#define NEGBIG -1000000000.0f

__device__ uint4 g_Bp[KC*64*32];        // [kc][n8pair][lane] packed b-fragments
__device__ uint4 g_wz4[1024*2*8*512];   // per-CTA z-GEMM partial (bf16-packed acc)
__device__ float g_ent[2];

__device__ __forceinline__ unsigned su32(const void* p){
  unsigned r; asm("{.reg .u64 t; cvta.to.shared.u64 t, %1; cvt.u32.u64 %0, t;}" : "=r"(r) : "l"(p)); return r; }
__device__ __forceinline__ ush f2b(float x){ return __bfloat16_as_ushort(__float2bfloat16_rn(x)); }
__device__ __forceinline__ float b2f(ush u){ return __bfloat162float(__ushort_as_bfloat16(u)); }
__device__ __forceinline__ float tanha(float x){ float y; asm("tanh.approx.f32 %0, %1;" : "=f"(y) : "f"(x)); return y; }
__device__ __forceinline__ float sigf(float x){ return fmaf(0.5f, tanha(0.5f*x), 0.5f); }
__device__ __forceinline__ unsigned pk2f(float lo,float hi){
  return (unsigned)__bfloat16_as_ushort(__float2bfloat16_rn(lo)) |
         ((unsigned)__bfloat16_as_ushort(__float2bfloat16_rn(hi))<<16); }
__device__ __forceinline__ float xlo(unsigned u){ return __uint_as_float(u<<16); }
__device__ __forceinline__ float xhi(unsigned u){ return __uint_as_float(u & 0xffff0000u); }

#define LDSM4(r0,r1,r2,r3,a) asm volatile( \
  "ldmatrix.sync.aligned.m8n8.x4.shared.b16 {%0,%1,%2,%3},[%4];" \
  : "=r"(r0),"=r"(r1),"=r"(r2),"=r"(r3) : "r"(a))
#define MMA(d,a0,a1,a2,a3,b0,b1) asm( \
  "mma.sync.aligned.m16n8k16.row.col.f32.bf16.bf16.f32 {%0,%1,%2,%3},{%4,%5,%6,%7},{%8,%9},{%0,%1,%2,%3};" \
  : "+f"(d[0]),"+f"(d[1]),"+f"(d[2]),"+f"(d[3]) : "r"(a0),"r"(a1),"r"(a2),"r"(a3),"r"(b0),"r"(b1))

// B' rows: k<256 Wz, k<512 Whh, k<528 Gp, k<532 Cbase, else 0. col=4*unit+gate.
__device__ float wval(int k,int grow,const float* Wih,const float* Whh,const float* ae,
                      const float* be,const float* ie,const float* bi,const float* bh){
  if (k<256) return Wih[grow*448+k];
  if (k<512) return Whh[grow*256+(k-256)];
  if (k<528){ float s=0.f; int p=k-512; for(int e=0;e<64;e++) s+=Wih[grow*448+384+e]*ae[p*64+e]; return s; }
  if (k<532){ int s4=k-528,br=s4>>1,ad=s4&1; float s=bi[grow]+bh[grow];
    for(int e=0;e<64;e++) s+=Wih[grow*448+256+e]*be[br*64+e];
    for(int e=0;e<64;e++) s+=Wih[grow*448+320+e]*ie[ad*64+e]; return s; }
  return 0.f;
}

__global__ void prep_bfrag(const float* Wih,const float* Whh,const float* ae,
                           const float* be,const float* ie,const float* bi,const float* bh){
  int idx = blockIdx.x*blockDim.x + threadIdx.x;
  if (idx==0){ g_ent[0]=0.f; g_ent[1]=0.f; }
  if (idx >= KC*64*32) return;
  int lane=idx&31, np=(idx>>5)&63, kc=idx>>11;
  int k0=(kc<<4)+((lane&3)<<1);
  uint4 b;
  #pragma unroll
  for (int s=0;s<2;s++){
    int n8=(np<<1)+s;
    int n=(n8<<3)+(lane>>2), grow=(n&3)*256+(n>>2);
    unsigned fx = pk2f(wval(k0  ,grow,Wih,Whh,ae,be,ie,bi,bh), wval(k0+1,grow,Wih,Whh,ae,be,ie,bi,bh));
    unsigned fy = pk2f(wval(k0+8,grow,Wih,Whh,ae,be,ie,bi,bh), wval(k0+9,grow,Wih,Whh,ae,be,ie,bi,bh));
    if (s==0){ b.x=fx; b.y=fy; } else { b.z=fx; b.w=fy; }
  }
  g_Bp[idx]=b;
}

__global__ void __launch_bounds__(NTH,1) decoder_kernel(
  const float* __restrict__ z1, const float* __restrict__ z2,
  const int* __restrict__ t_act, const int* __restrict__ m_act,
  const float* __restrict__ Wt, const float* __restrict__ bt,
  const float* __restrict__ Wm, const float* __restrict__ bm,
  float* __restrict__ out)
{
  extern __shared__ ush A[];                 // [64][ASTR] bf16
  float* Csm = (float*)(A + RB*ASTR);        // [64][CSTR] f32
  __shared__ int   s_pidx[RB], s_mask[RB];
  __shared__ float s_lp[RB], s_red[32];

  const int t=threadIdx.x, wid=t>>5, lane=t&31;
  const int r0=blockIdx.x*RB;
  const unsigned abase=su32(A);
  const int rowA=lane&15, kadj=(lane>>4)<<3;
  const int mtb=(wid>>3)<<1;
  const int n8w=(wid&7)<<3;
  float eT=0.f, eM=0.f;

  for (int i=t;i<RB*ASTR;i+=NTH) A[i]=0;
  for (int i=t;i<RB*CSTR;i+=NTH) Csm[i]=0.f;
  for (int i=t;i<RB*256;i+=NTH)
    A[(i>>8)*ASTR+(i&255)] = f2b(z1[(size_t)(r0+(i>>8))*256+(i&255)]);
  if (t<RB){ s_pidx[t]=15; s_mask[t]=15; s_lp[t]=0.f;
             A[t*ASTR+768+15]=0x3F80; A[t*ASTR+784]=0x3F80; }

  for (int ss=0; ss<16; ss++){
    const int hin = 256+((ss&1)<<8), hout = 256+((1-(ss&1))<<8);
    const bool bstart = (ss==0)||(ss==8);
    __syncthreads();
    #pragma unroll 1
    for (int pass=0; pass<2; pass++){
      const int n8b = (pass<<6)+n8w;
      uint4* wzp = g_wz4 + ((size_t)(blockIdx.x*2+pass)*8)*512 + t;
      float acc[8][2][4];
      if (bstart){
        #pragma unroll
        for (int j=0;j<8;j++)
          #pragma unroll
          for (int m=0;m<2;m++){ acc[j][m][0]=0.f; acc[j][m][1]=0.f; acc[j][m][2]=0.f; acc[j][m][3]=0.f; }
        // z chunks
        #pragma unroll 2
        for (int kc=0;kc<16;kc++){
          int kb = kc<<4;
          unsigned a0[2],a1[2],a2[2],a3[2];
          #pragma unroll
          for (int m=0;m<2;m++){
            unsigned aa = abase + (unsigned)(((((mtb+m)<<4)+rowA)*ASTR + kb + kadj)<<1);
            LDSM4(a0[m],a1[m],a2[m],a3[m],aa);
          }
          const uint4* bp = g_Bp + ((size_t)(kc<<6)+(n8b>>1))*32 + lane;
          #pragma unroll
          for (int jp=0;jp<4;jp++){
            uint4 b = bp[jp<<5];
            #pragma unroll
            for (int m=0;m<2;m++){
              MMA(acc[2*jp  ][m], a0[m],a1[m],a2[m],a3[m], b.x, b.y);
              MMA(acc[2*jp+1][m], a0[m],a1[m],a2[m],a3[m], b.z, b.w);
            }
          }
        }
        // snapshot z-partial (bf16)
        #pragma unroll
        for (int j=0;j<8;j++){
          uint4 s;
          s.x = pk2f(acc[j][0][0],acc[j][0][1]);
          s.y = pk2f(acc[j][0][2],acc[j][0][3]);
          s.z = pk2f(acc[j][1][0],acc[j][1][1]);
          s.w = pk2f(acc[j][1][2],acc[j][1][3]);
          wzp[(size_t)j*512] = s;
        }
      } else {
        #pragma unroll
        for (int j=0;j<8;j++){
          uint4 s = wzp[(size_t)j*512];
          acc[j][0][0]=xlo(s.x); acc[j][0][1]=xhi(s.x);
          acc[j][0][2]=xlo(s.y); acc[j][0][3]=xhi(s.y);
          acc[j][1][0]=xlo(s.z); acc[j][1][1]=xhi(s.z);
          acc[j][1][2]=xlo(s.w); acc[j][1][3]=xhi(s.w);
        }
      }
      // h + onehot chunks
      #pragma unroll 2
      for (int kc=16;kc<KC;kc++){
        int kb = kc<32 ? hin+((kc-16)<<4) : (kc==32?768:784);
        unsigned a0[2],a1[2],a2[2],a3[2];
        #pragma unroll
        for (int m=0;m<2;m++){
          unsigned aa = abase + (unsigned)(((((mtb+m)<<4)+rowA)*ASTR + kb + kadj)<<1);
          LDSM4(a0[m],a1[m],a2[m],a3[m],aa);
        }
        const uint4* bp = g_Bp + ((size_t)(kc<<6)+(n8b>>1))*32 + lane;
        #pragma unroll
        for (int jp=0;jp<4;jp++){
          uint4 b = bp[jp<<5];
          #pragma unroll
          for (int m=0;m<2;m++){
            MMA(acc[2*jp  ][m], a0[m],a1[m],a2[m],a3[m], b.x, b.y);
            MMA(acc[2*jp+1][m], a0[m],a1[m],a2[m],a3[m], b.z, b.w);
          }
        }
      }
      #pragma unroll
      for (int j=0;j<8;j++){
        int n8=n8b+j;
        #pragma unroll
        for (int m=0;m<2;m++){
          float c0=acc[j][m][0],c1=acc[j][m][1],c2=acc[j][m][2],c3=acc[j][m][3];
          float t0=__shfl_xor_sync(~0u,c0,1), t1=__shfl_xor_sync(~0u,c1,1);
          float t2=__shfl_xor_sync(~0u,c2,1), t3=__shfl_xor_sync(~0u,c3,1);
          float gi_,gf_,gg_,go_; int row;
          if (lane&1){ gi_=t2; gf_=t3; gg_=c2; go_=c3; row=((mtb+m)<<4)+(lane>>2)+8; }
          else       { gi_=c0; gf_=c1; gg_=t0; go_=t1; row=((mtb+m)<<4)+(lane>>2); }
          int u=(n8<<1)|((lane>>1)&1);
          float cn = sigf(gf_)*Csm[row*CSTR+u] + sigf(gi_)*tanha(gg_);
          Csm[row*CSTR+u]=cn;
          A[row*ASTR+hout+u]=f2b(sigf(go_)*tanha(cn));
        }
      }
    }
    __syncthreads();

    const int branch=ss>>3, isM=ss&1, step=(ss>>1)&3;
    for (int rr=0;rr<4;rr++){
      int r=(wid<<2)+rr;
      const ush* hr = A + r*ASTR + hout;
      if (!isM){
        float a0=0.f,a1=0.f,a2=0.f,a3=0.f;
        #pragma unroll
        for (int kk=0;kk<8;kk++){
          int k=lane+(kk<<5); float hv=b2f(hr[k]);
          a0+=Wt[k]*hv; a1+=Wt[256+k]*hv; a2+=Wt[512+k]*hv; a3+=Wt[768+k]*hv;
        }
        #pragma unroll
        for (int o=16;o;o>>=1){
          a0+=__shfl_xor_sync(~0u,a0,o); a1+=__shfl_xor_sync(~0u,a1,o);
          a2+=__shfl_xor_sync(~0u,a2,o); a3+=__shfl_xor_sync(~0u,a3,o);
        }
        int mk=s_mask[r];
        float l0=(mk&1)?a0+bt[0]:NEGBIG, l1=(mk&2)?a1+bt[1]:NEGBIG;
        float l2=(mk&4)?a2+bt[2]:NEGBIG, l3=(mk&8)?a3+bt[3]:NEGBIG;
        float mx=fmaxf(fmaxf(l0,l1),fmaxf(l2,l3));
        float e0=__expf(l0-mx),e1=__expf(l1-mx),e2=__expf(l2-mx),e3=__expf(l3-mx);
        float se=e0+e1+e2+e3, sl=e0*l0+e1*l1+e2*l2+e3*l3, lse=mx+__logf(se);
        int ta=t_act[(size_t)(r0+r)*8+branch*4+step];
        float lsel=(ta==0)?l0:(ta==1)?l1:(ta==2)?l2:l3;
        if (lane==0){
          s_lp[r]+=lsel-lse; s_mask[r]=mk&~(1<<ta); eT+=lse-sl/se;
          A[r*ASTR+768+s_pidx[r]]=0; A[r*ASTR+768+ta]=0x3F80; s_pidx[r]=ta;
        }
      } else {
        float a[NMM];
        #pragma unroll
        for (int j=0;j<NMM;j++) a[j]=0.f;
        #pragma unroll
        for (int kk=0;kk<8;kk++){
          int k=lane+(kk<<5); float hv=b2f(hr[k]);
          #pragma unroll
          for (int j=0;j<NMM;j++) a[j]+=Wm[j*256+k]*hv;
        }
        #pragma unroll
        for (int j=0;j<NMM;j++)
          #pragma unroll
          for (int o=16;o;o>>=1) a[j]+=__shfl_xor_sync(~0u,a[j],o);
        float mx=-1e30f;
        #pragma unroll
        for (int j=0;j<NMM;j++){ a[j]+=bm[j]; mx=fmaxf(mx,a[j]); }
        float se=0.f,sl=0.f;
        #pragma unroll
        for (int j=0;j<NMM;j++){ float e=__expf(a[j]-mx); se+=e; sl+=e*a[j]; }
        float lse=mx+__logf(se);
        int ma=m_act[(size_t)(r0+r)*8+branch*4+step];
        float lsel=a[0];
        #pragma unroll
        for (int j=1;j<NMM;j++) lsel=(j==ma)?a[j]:lsel;
        if (lane==0){
          s_lp[r]+=lsel-lse; eM+=lse-sl/se;
          A[r*ASTR+768+s_pidx[r]]=0; A[r*ASTR+768+ma]=0x3F80; s_pidx[r]=ma;
        }
      }
    }
    if (ss<15 && t<RB){
      int sc=((ss>>3)<<1)|(ss&1), sn=(((ss+1)>>3)<<1)|((ss+1)&1);
      A[t*ASTR+784+sc]=0; A[t*ASTR+784+sn]=0x3F80;
    }
    if (ss==7){
      for (int i=t;i<RB*256;i+=NTH)
        A[(i>>8)*ASTR+(i&255)] = f2b(z2[(size_t)(r0+(i>>8))*256+(i&255)]);
      if (t<RB) s_mask[t]=15;
    }
  }

  __syncthreads();
  if (t<RB) out[r0+t]=s_lp[t];
  if (lane==0){ s_red[wid]=eT; s_red[16+wid]=eM; }
  __syncthreads();
  if (t==0){
    float sT=0.f,sM=0.f;
    for (int w=0;w<16;w++){ sT+=s_red[w]; sM+=s_red[16+w]; }
    atomicAdd(&g_ent[0],sT); atomicAdd(&g_ent[1],sM);
  }
}

__global__ void finalize_kernel(float* out,int off){
  if (threadIdx.x==0 && blockIdx.x==0){
    const float sc=1.0f/(65536.0f*8.0f);
    out[off]=g_ent[0]*sc; out[off+1]=g_ent[1]*sc;
  }
}
__global__ void cvt_kernel(const int* ti,const int* mi,float* out){
  int i=blockIdx.x*blockDim.x+threadIdx.x;
  if (i<65536*8){ out[65536+i]=(float)ti[i]; out[65536+65536*8+i]=(float)mi[i]; }
}

extern "C" void kernel_launch(void* const* d_in, const int* in_sizes, int n_in,
                              void* d_out, int out_size)
{
  (void)in_sizes; (void)n_in;
  const float* z1=(const float*)d_in[0];  const float* z2=(const float*)d_in[1];
  const int* t_act=(const int*)d_in[2];   const int* m_act=(const int*)d_in[3];
  const float* aemb=(const float*)d_in[4];const float* bemb=(const float*)d_in[5];
  const float* idemb=(const float*)d_in[6];
  const float* Wih=(const float*)d_in[7]; const float* Whh=(const float*)d_in[8];
  const float* bih=(const float*)d_in[9]; const float* bhh=(const float*)d_in[10];
  const float* Wt=(const float*)d_in[11]; const float* bt=(const float*)d_in[12];
  const float* Wm=(const float*)d_in[13]; const float* bm=(const float*)d_in[14];
  float* out=(float*)d_out;

  const int SMEM = RB*ASTR*2 + RB*CSTR*4;
  cudaFuncSetAttribute(decoder_kernel, cudaFuncAttributeMaxDynamicSharedMemorySize, SMEM);

  prep_bfrag<<<(KC*64*32+255)/256,256>>>(Wih,Whh,aemb,bemb,idemb,bih,bhh);
  decoder_kernel<<<65536/RB, NTH, SMEM>>>(z1,z2,t_act,m_act,Wt,bt,Wm,bm,out);

  const int NACT=65536*8;
  if (out_size >= 65536+2*NACT+2){
    cvt_kernel<<<(NACT+255)/256,256>>>(t_act,m_act,out);
    finalize_kernel<<<1,32>>>(out,65536+2*NACT);
  } else if (out_size >= 65536+2){
    finalize_kernel<<<1,32>>>(out,65536);
  }
}